// round 2
// baseline (speedup 1.0000x reference)
#include <cuda_runtime.h>
#include <cstdint>

#define B_      2
#define CIN     256
#define Hdim    128
#define Wdim    128
#define KQ      128
#define HW      16384
#define NTOT    21504   // 16384 + 4096 + 1024
#define SCALE   0.08838834764831845f  // 128^-0.5

// ---------------- device scratch (static, no runtime alloc) ----------------
__device__ float g_wT [CIN * 9 * KQ];          // conv weights: [c][tap][k]
__device__ float g_kwT[KQ * KQ];               // key_w^T: [c][k]
__device__ float g_qwT[KQ * KQ];               // query_w^T: [c][k]
__device__ float g_x   [B_ * HW * KQ];         // conv out: [b*m][k]
__device__ float g_keys[B_ * HW * KQ];         // [b*m][k]
__device__ float g_qrs [B_ * HW * KQ];
__device__ float g_k2[B_ * 4096 * KQ], g_q2[B_ * 4096 * KQ];
__device__ float g_k4[B_ * 1024 * KQ], g_q4[B_ * 1024 * KQ];

// ---------------- weight transposes ----------------
__global__ __launch_bounds__(256) void prep_w(const float* __restrict__ conv_w,
                                              const float* __restrict__ key_w,
                                              const float* __restrict__ query_w) {
    int i = blockIdx.x * 256 + threadIdx.x;
    if (i < CIN * 9 * KQ) {
        int k = i % KQ;
        int t = (i / KQ) % 9;
        int c = i / (KQ * 9);
        g_wT[i] = conv_w[(k * CIN + c) * 9 + t];
    }
    if (i < KQ * KQ) {
        int k = i % KQ, c = i / KQ;
        g_kwT[i] = key_w[k * KQ + c];
        g_qwT[i] = query_w[k * KQ + c];
    }
}

// ---------------- 3x3 SAME conv (zero pad), fp32 tiled ----------------
// CTA: 2 rows x 32 cols spatial tile, all 128 out channels.
// thread: 8 spatial (one row, 8 consecutive cols) x 4 channels.
__global__ __launch_bounds__(256) void conv3x3(const float* __restrict__ feats,
                                               const float* __restrict__ conv_b) {
    __shared__ float s_in[8 * 4 * 34];   // [cc][y(4)][x(34)]
    __shared__ float s_w [8 * 9 * 128];  // [cc][tap][k]

    const int b   = blockIdx.z;
    const int ty0 = blockIdx.y * 2;
    const int tx0 = blockIdx.x * 32;
    const int tid = threadIdx.x;
    const int grp = tid >> 5;            // 0..7
    const int tr  = grp >> 2;            // row within tile: 0/1
    const int tcb = (grp & 3) * 8;       // col base within tile
    const int kb  = (tid & 31) * 4;      // out-channel base

    float acc[8][4];
    #pragma unroll
    for (int i = 0; i < 8; i++)
        #pragma unroll
        for (int j = 0; j < 4; j++) acc[i][j] = conv_b[kb + j];

    for (int c0 = 0; c0 < CIN; c0 += 8) {
        __syncthreads();
        // input tile: 8 ch x 4 rows x 34 cols, zero-padded at borders
        for (int idx = tid; idx < 8 * 136; idx += 256) {
            int cc  = idx / 136;
            int rem = idx % 136;
            int y = rem / 34, x = rem % 34;
            int gy = ty0 + y - 1, gx = tx0 + x - 1;
            float v = 0.f;
            if (gy >= 0 && gy < Hdim && gx >= 0 && gx < Wdim)
                v = feats[(((size_t)b * CIN + c0 + cc) * Hdim + gy) * Wdim + gx];
            s_in[idx] = v;
        }
        // weights: contiguous copy of 9216 floats from g_wT
        {
            const float4* src = (const float4*)(g_wT + (size_t)c0 * 9 * KQ);
            float4* dst = (float4*)s_w;
            for (int idx = tid; idx < 2304; idx += 256) dst[idx] = src[idx];
        }
        __syncthreads();

        #pragma unroll
        for (int cc = 0; cc < 8; cc++) {
            #pragma unroll
            for (int dy = 0; dy < 3; dy++) {
                float r[10];
                #pragma unroll
                for (int ii = 0; ii < 10; ii++)
                    r[ii] = s_in[cc * 136 + (tr + dy) * 34 + tcb + ii];
                #pragma unroll
                for (int dx = 0; dx < 3; dx++) {
                    float4 wv = *(const float4*)&s_w[cc * 1152 + (dy * 3 + dx) * 128 + kb];
                    #pragma unroll
                    for (int i = 0; i < 8; i++) {
                        float a = r[i + dx];
                        acc[i][0] += a * wv.x;
                        acc[i][1] += a * wv.y;
                        acc[i][2] += a * wv.z;
                        acc[i][3] += a * wv.w;
                    }
                }
            }
        }
    }

    #pragma unroll
    for (int i = 0; i < 8; i++) {
        int m = (ty0 + tr) * Wdim + tx0 + tcb + i;
        float4 v = make_float4(acc[i][0], acc[i][1], acc[i][2], acc[i][3]);
        *(float4*)&g_x[((size_t)b * HW + m) * KQ + kb] = v;
    }
}

// ---------------- key/query projections: out[m][k] = sum_c x[m][c]*wT[c][k]+b[k]
__global__ __launch_bounds__(256) void proj(const float* __restrict__ key_b,
                                            const float* __restrict__ query_b) {
    __shared__ float s_a[32][65];     // [c][m] padded
    __shared__ float s_b[32 * 128];   // [c][k]

    const int which = blockIdx.y;     // 0: keys, 1: queries
    const float* wT   = which ? g_qwT : g_kwT;
    const float* bias = which ? query_b : key_b;
    float* out        = which ? g_qrs : g_keys;

    const size_t mbase = (size_t)blockIdx.x * 64;   // over B_*HW
    const int tid = threadIdx.x;
    const int grp = tid >> 5;
    const int kbb = (tid & 31) * 4;

    float acc[8][4];
    #pragma unroll
    for (int i = 0; i < 8; i++)
        #pragma unroll
        for (int j = 0; j < 4; j++) acc[i][j] = bias[kbb + j];

    for (int c0 = 0; c0 < KQ; c0 += 32) {
        __syncthreads();
        {   // A tile: 64 m x 32 c (transpose into [c][m])
            int m = tid >> 3;          // 0..31
            int l = tid & 7;           // c-group (4 floats)
            #pragma unroll
            for (int half = 0; half < 2; half++) {
                int mm = m + half * 32;
                float4 v = *(const float4*)&g_x[(mbase + mm) * KQ + c0 + l * 4];
                s_a[l * 4 + 0][mm] = v.x;
                s_a[l * 4 + 1][mm] = v.y;
                s_a[l * 4 + 2][mm] = v.z;
                s_a[l * 4 + 3][mm] = v.w;
            }
        }
        {   // B tile: 32 c x 128 k, contiguous from wT
            const float4* src = (const float4*)(wT + (size_t)c0 * KQ);
            float4* dst = (float4*)s_b;
            for (int idx = tid; idx < 1024; idx += 256) dst[idx] = src[idx];
        }
        __syncthreads();

        #pragma unroll
        for (int cc = 0; cc < 32; cc++) {
            float4 wv = *(const float4*)&s_b[cc * 128 + kbb];
            #pragma unroll
            for (int i = 0; i < 8; i++) {
                float a = s_a[cc][grp * 8 + i];
                acc[i][0] += a * wv.x;
                acc[i][1] += a * wv.y;
                acc[i][2] += a * wv.z;
                acc[i][3] += a * wv.w;
            }
        }
    }

    #pragma unroll
    for (int i = 0; i < 8; i++) {
        float4 v = make_float4(acc[i][0], acc[i][1], acc[i][2], acc[i][3]);
        *(float4*)&out[(mbase + grp * 8 + i) * KQ + kbb] = v;
    }
}

// ---------------- avg pool s x s, [b][m][c] -> [b][n][c] ----------------
__global__ __launch_bounds__(256) void pool_kernel(int s) {
    const float* in = blockIdx.z ? g_qrs : g_keys;
    float* out;
    const int hp = Hdim / s;
    const int n  = hp * hp;
    if (s == 2) out = blockIdx.z ? g_q2 : g_k2;
    else        out = blockIdx.z ? g_q4 : g_k4;

    int idx = blockIdx.x * 256 + threadIdx.x;   // float4 units
    if (idx >= B_ * n * 32) return;
    int c4 = idx & 31;
    int nn = (idx >> 5) % n;
    int b  = idx / (n * 32);
    int y = nn / hp, x = nn % hp;

    float4 acc = make_float4(0.f, 0.f, 0.f, 0.f);
    for (int ry = 0; ry < s; ry++)
        for (int rx = 0; rx < s; rx++) {
            int m = (y * s + ry) * Wdim + x * s + rx;
            float4 v = *(const float4*)&in[((size_t)b * HW + m) * KQ + c4 * 4];
            acc.x += v.x; acc.y += v.y; acc.z += v.z; acc.w += v.w;
        }
    float inv = 1.f / (float)(s * s);
    acc.x *= inv; acc.y *= inv; acc.z *= inv; acc.w *= inv;
    *(float4*)&out[((size_t)b * n + nn) * KQ + c4 * 4] = acc;
}

// ---------------- logits: warp per position, lane splits channels ----------------
__global__ __launch_bounds__(256) void logits_kernel(const int* __restrict__ inds,
                                                     float* __restrict__ out,
                                                     int n, int n_off, int lvl) {
    const float* q;
    const float* k;
    if (lvl == 0)      { q = g_qrs; k = g_keys; }
    else if (lvl == 1) { q = g_q2;  k = g_k2;  }
    else               { q = g_q4;  k = g_k4;  }

    const int warp = threadIdx.x >> 5;
    const int lane = threadIdx.x & 31;
    const int nn = blockIdx.x * 8 + warp;
    const int b  = blockIdx.z;
    if (nn >= n) return;

    float4 qv = *(const float4*)&q[((size_t)b * n + nn) * KQ + lane * 4];
    const int* ip = inds + ((size_t)b * n + nn) * 32;

    float myval = 0.f;
    #pragma unroll 4
    for (int s = 0; s < 32; s++) {
        int ind = ip[s];
        float4 kv = *(const float4*)&k[((size_t)b * n + ind) * KQ + lane * 4];
        float p = qv.x * kv.x + qv.y * kv.y + qv.z * kv.z + qv.w * kv.w;
        p += __shfl_xor_sync(0xffffffffu, p, 1);
        p += __shfl_xor_sync(0xffffffffu, p, 2);
        p += __shfl_xor_sync(0xffffffffu, p, 4);
        p += __shfl_xor_sync(0xffffffffu, p, 8);
        p += __shfl_xor_sync(0xffffffffu, p, 16);
        if (lane == s) myval = p * SCALE;
    }
    out[((size_t)b * NTOT + n_off + nn) * 32 + lane] = myval;
}

// ---------------- launch ----------------
extern "C" void kernel_launch(void* const* d_in, const int* in_sizes, int n_in,
                              void* d_out, int out_size) {
    const float* feats   = (const float*)d_in[0];
    const float* conv_w  = (const float*)d_in[1];
    const float* conv_b  = (const float*)d_in[2];
    const float* key_w   = (const float*)d_in[3];
    const float* key_b   = (const float*)d_in[4];
    const float* query_w = (const float*)d_in[5];
    const float* query_b = (const float*)d_in[6];
    const int* si2 = (const int*)d_in[7];
    const int* si3 = (const int*)d_in[8];
    const int* si4 = (const int*)d_in[9];
    float* out = (float*)d_out;

    prep_w<<<1152, 256>>>(conv_w, key_w, query_w);
    conv3x3<<<dim3(Wdim / 32, Hdim / 2, B_), 256>>>(feats, conv_b);
    proj<<<dim3((B_ * HW) / 64, 2, 1), 256>>>(key_b, query_b);
    pool_kernel<<<dim3((B_ * 4096 * 32 + 255) / 256, 1, 2), 256>>>(2);
    pool_kernel<<<dim3((B_ * 1024 * 32 + 255) / 256, 1, 2), 256>>>(4);
    logits_kernel<<<dim3(16384 / 8, 1, B_), 256>>>(si2, out, 16384, 0, 0);
    logits_kernel<<<dim3(4096 / 8, 1, B_), 256>>>(si3, out, 4096, 16384, 1);
    logits_kernel<<<dim3(1024 / 8, 1, B_), 256>>>(si4, out, 1024, 20480, 2);
}

// round 3
// speedup vs baseline: 1.0006x; 1.0006x over previous
#include <cuda_runtime.h>
#include <cstdint>

#define B_      2
#define CIN     256
#define Hdim    128
#define Wdim    128
#define KQ      128
#define HW      16384
#define NTOT    21504   // 16384 + 4096 + 1024
#define SCALE   0.08838834764831845f  // 128^-0.5

// ---------------- device scratch (static, no runtime alloc) ----------------
__device__ float g_wT [CIN * 9 * KQ];          // conv weights: [c][tap][k]
__device__ float g_kwT[KQ * KQ];               // key_w^T: [c][k]
__device__ float g_qwT[KQ * KQ];               // query_w^T: [c][k]
__device__ float g_x   [B_ * HW * KQ];         // conv out: [b*m][k]
__device__ float g_keys[B_ * HW * KQ];         // [b*m][k]
__device__ float g_qrs [B_ * HW * KQ];
__device__ float g_k2[B_ * 4096 * KQ], g_q2[B_ * 4096 * KQ];
__device__ float g_k4[B_ * 1024 * KQ], g_q4[B_ * 1024 * KQ];

// ---------------- weight transposes ----------------
__global__ __launch_bounds__(256) void prep_w(const float* __restrict__ conv_w,
                                              const float* __restrict__ key_w,
                                              const float* __restrict__ query_w) {
    int i = blockIdx.x * 256 + threadIdx.x;
    if (i < CIN * 9 * KQ) {
        int k = i % KQ;
        int t = (i / KQ) % 9;
        int c = i / (KQ * 9);
        g_wT[i] = conv_w[(k * CIN + c) * 9 + t];
    }
    if (i < KQ * KQ) {
        int k = i % KQ, c = i / KQ;
        g_kwT[i] = key_w[k * KQ + c];
        g_qwT[i] = query_w[k * KQ + c];
    }
}

// ---------------- 3x3 SAME conv (zero pad), fp32 tiled ----------------
// CTA: 2 rows x 32 cols spatial tile, all 128 out channels.
// thread: 8 spatial (one row, 8 consecutive cols) x 4 channels.
__global__ __launch_bounds__(256) void conv3x3(const float* __restrict__ feats,
                                               const float* __restrict__ conv_b) {
    __shared__ float s_in[8 * 4 * 34];   // [cc][y(4)][x(34)]
    __shared__ float s_w [8 * 9 * 128];  // [cc][tap][k]

    const int b   = blockIdx.z;
    const int ty0 = blockIdx.y * 2;
    const int tx0 = blockIdx.x * 32;
    const int tid = threadIdx.x;
    const int grp = tid >> 5;            // 0..7
    const int tr  = grp >> 2;            // row within tile: 0/1
    const int tcb = (grp & 3) * 8;       // col base within tile
    const int kb  = (tid & 31) * 4;      // out-channel base

    float acc[8][4];
    #pragma unroll
    for (int i = 0; i < 8; i++)
        #pragma unroll
        for (int j = 0; j < 4; j++) acc[i][j] = conv_b[kb + j];

    for (int c0 = 0; c0 < CIN; c0 += 8) {
        __syncthreads();
        // input tile: 8 ch x 4 rows x 34 cols, zero-padded at borders
        for (int idx = tid; idx < 8 * 136; idx += 256) {
            int cc  = idx / 136;
            int rem = idx % 136;
            int y = rem / 34, x = rem % 34;
            int gy = ty0 + y - 1, gx = tx0 + x - 1;
            float v = 0.f;
            if (gy >= 0 && gy < Hdim && gx >= 0 && gx < Wdim)
                v = feats[(((size_t)b * CIN + c0 + cc) * Hdim + gy) * Wdim + gx];
            s_in[idx] = v;
        }
        // weights: contiguous copy of 9216 floats from g_wT
        {
            const float4* src = (const float4*)(g_wT + (size_t)c0 * 9 * KQ);
            float4* dst = (float4*)s_w;
            for (int idx = tid; idx < 2304; idx += 256) dst[idx] = src[idx];
        }
        __syncthreads();

        #pragma unroll
        for (int cc = 0; cc < 8; cc++) {
            #pragma unroll
            for (int dy = 0; dy < 3; dy++) {
                float r[10];
                #pragma unroll
                for (int ii = 0; ii < 10; ii++)
                    r[ii] = s_in[cc * 136 + (tr + dy) * 34 + tcb + ii];
                #pragma unroll
                for (int dx = 0; dx < 3; dx++) {
                    float4 wv = *(const float4*)&s_w[cc * 1152 + (dy * 3 + dx) * 128 + kb];
                    #pragma unroll
                    for (int i = 0; i < 8; i++) {
                        float a = r[i + dx];
                        acc[i][0] += a * wv.x;
                        acc[i][1] += a * wv.y;
                        acc[i][2] += a * wv.z;
                        acc[i][3] += a * wv.w;
                    }
                }
            }
        }
    }

    #pragma unroll
    for (int i = 0; i < 8; i++) {
        int m = (ty0 + tr) * Wdim + tx0 + tcb + i;
        float4 v = make_float4(acc[i][0], acc[i][1], acc[i][2], acc[i][3]);
        *(float4*)&g_x[((size_t)b * HW + m) * KQ + kb] = v;
    }
}

// ---------------- key/query projections: out[m][k] = sum_c x[m][c]*wT[c][k]+b[k]
__global__ __launch_bounds__(256) void proj(const float* __restrict__ key_b,
                                            const float* __restrict__ query_b) {
    __shared__ float s_a[32][65];     // [c][m] padded
    __shared__ float s_b[32 * 128];   // [c][k]

    const int which = blockIdx.y;     // 0: keys, 1: queries
    const float* wT   = which ? g_qwT : g_kwT;
    const float* bias = which ? query_b : key_b;
    float* out        = which ? g_qrs : g_keys;

    const size_t mbase = (size_t)blockIdx.x * 64;   // over B_*HW
    const int tid = threadIdx.x;
    const int grp = tid >> 5;
    const int kbb = (tid & 31) * 4;

    float acc[8][4];
    #pragma unroll
    for (int i = 0; i < 8; i++)
        #pragma unroll
        for (int j = 0; j < 4; j++) acc[i][j] = bias[kbb + j];

    for (int c0 = 0; c0 < KQ; c0 += 32) {
        __syncthreads();
        {   // A tile: 64 m x 32 c (transpose into [c][m])
            int m = tid >> 3;          // 0..31
            int l = tid & 7;           // c-group (4 floats)
            #pragma unroll
            for (int half = 0; half < 2; half++) {
                int mm = m + half * 32;
                float4 v = *(const float4*)&g_x[(mbase + mm) * KQ + c0 + l * 4];
                s_a[l * 4 + 0][mm] = v.x;
                s_a[l * 4 + 1][mm] = v.y;
                s_a[l * 4 + 2][mm] = v.z;
                s_a[l * 4 + 3][mm] = v.w;
            }
        }
        {   // B tile: 32 c x 128 k, contiguous from wT
            const float4* src = (const float4*)(wT + (size_t)c0 * KQ);
            float4* dst = (float4*)s_b;
            for (int idx = tid; idx < 1024; idx += 256) dst[idx] = src[idx];
        }
        __syncthreads();

        #pragma unroll
        for (int cc = 0; cc < 32; cc++) {
            float4 wv = *(const float4*)&s_b[cc * 128 + kbb];
            #pragma unroll
            for (int i = 0; i < 8; i++) {
                float a = s_a[cc][grp * 8 + i];
                acc[i][0] += a * wv.x;
                acc[i][1] += a * wv.y;
                acc[i][2] += a * wv.z;
                acc[i][3] += a * wv.w;
            }
        }
    }

    #pragma unroll
    for (int i = 0; i < 8; i++) {
        float4 v = make_float4(acc[i][0], acc[i][1], acc[i][2], acc[i][3]);
        *(float4*)&out[(mbase + grp * 8 + i) * KQ + kbb] = v;
    }
}

// ---------------- avg pool s x s, [b][m][c] -> [b][n][c] ----------------
__global__ __launch_bounds__(256) void pool_kernel(int s) {
    const float* in = blockIdx.z ? g_qrs : g_keys;
    float* out;
    const int hp = Hdim / s;
    const int n  = hp * hp;
    if (s == 2) out = blockIdx.z ? g_q2 : g_k2;
    else        out = blockIdx.z ? g_q4 : g_k4;

    int idx = blockIdx.x * 256 + threadIdx.x;   // float4 units
    if (idx >= B_ * n * 32) return;
    int c4 = idx & 31;
    int nn = (idx >> 5) % n;
    int b  = idx / (n * 32);
    int y = nn / hp, x = nn % hp;

    float4 acc = make_float4(0.f, 0.f, 0.f, 0.f);
    for (int ry = 0; ry < s; ry++)
        for (int rx = 0; rx < s; rx++) {
            int m = (y * s + ry) * Wdim + x * s + rx;
            float4 v = *(const float4*)&in[((size_t)b * HW + m) * KQ + c4 * 4];
            acc.x += v.x; acc.y += v.y; acc.z += v.z; acc.w += v.w;
        }
    float inv = 1.f / (float)(s * s);
    acc.x *= inv; acc.y *= inv; acc.z *= inv; acc.w *= inv;
    *(float4*)&out[((size_t)b * n + nn) * KQ + c4 * 4] = acc;
}

// ---------------- logits: warp per position, lane splits channels ----------------
__global__ __launch_bounds__(256) void logits_kernel(const int* __restrict__ inds,
                                                     float* __restrict__ out,
                                                     int n, int n_off, int lvl) {
    const float* q;
    const float* k;
    if (lvl == 0)      { q = g_qrs; k = g_keys; }
    else if (lvl == 1) { q = g_q2;  k = g_k2;  }
    else               { q = g_q4;  k = g_k4;  }

    const int warp = threadIdx.x >> 5;
    const int lane = threadIdx.x & 31;
    const int nn = blockIdx.x * 8 + warp;
    const int b  = blockIdx.z;
    if (nn >= n) return;

    float4 qv = *(const float4*)&q[((size_t)b * n + nn) * KQ + lane * 4];
    const int* ip = inds + ((size_t)b * n + nn) * 32;

    float myval = 0.f;
    #pragma unroll 4
    for (int s = 0; s < 32; s++) {
        int ind = ip[s];
        float4 kv = *(const float4*)&k[((size_t)b * n + ind) * KQ + lane * 4];
        float p = qv.x * kv.x + qv.y * kv.y + qv.z * kv.z + qv.w * kv.w;
        p += __shfl_xor_sync(0xffffffffu, p, 1);
        p += __shfl_xor_sync(0xffffffffu, p, 2);
        p += __shfl_xor_sync(0xffffffffu, p, 4);
        p += __shfl_xor_sync(0xffffffffu, p, 8);
        p += __shfl_xor_sync(0xffffffffu, p, 16);
        if (lane == s) myval = p * SCALE;
    }
    out[((size_t)b * NTOT + n_off + nn) * 32 + lane] = myval;
}

// ---------------- launch ----------------
extern "C" void kernel_launch(void* const* d_in, const int* in_sizes, int n_in,
                              void* d_out, int out_size) {
    const float* feats   = (const float*)d_in[0];
    const float* conv_w  = (const float*)d_in[1];
    const float* conv_b  = (const float*)d_in[2];
    const float* key_w   = (const float*)d_in[3];
    const float* key_b   = (const float*)d_in[4];
    const float* query_w = (const float*)d_in[5];
    const float* query_b = (const float*)d_in[6];
    const int* si2 = (const int*)d_in[7];
    const int* si3 = (const int*)d_in[8];
    const int* si4 = (const int*)d_in[9];
    float* out = (float*)d_out;

    prep_w<<<1152, 256>>>(conv_w, key_w, query_w);
    conv3x3<<<dim3(Wdim / 32, Hdim / 2, B_), 256>>>(feats, conv_b);
    proj<<<dim3((B_ * HW) / 64, 2, 1), 256>>>(key_b, query_b);
    pool_kernel<<<dim3((B_ * 4096 * 32 + 255) / 256, 1, 2), 256>>>(2);
    pool_kernel<<<dim3((B_ * 1024 * 32 + 255) / 256, 1, 2), 256>>>(4);
    logits_kernel<<<dim3(16384 / 8, 1, B_), 256>>>(si2, out, 16384, 0, 0);
    logits_kernel<<<dim3(4096 / 8, 1, B_), 256>>>(si3, out, 4096, 16384, 1);
    logits_kernel<<<dim3(1024 / 8, 1, B_), 256>>>(si4, out, 1024, 20480, 2);
}

// round 5
// speedup vs baseline: 2.2238x; 2.2224x over previous
#include <cuda_runtime.h>
#include <cuda_bf16.h>
#include <cstdint>

#define B_      2
#define CIN     256
#define Hdim    128
#define Wdim    128
#define KQ      128
#define HW      16384
#define NTOT    21504   // 16384 + 4096 + 1024
#define SCALE   0.08838834764831845f
#define PADW    130
#define PADN    16900   // 130*130

#define SMEM_BYTES 131072
#define SW(o) ((uint32_t)(o) ^ ((((uint32_t)(o)) >> 3) & 0x70u))

// ---------------- device scratch ----------------
__device__ __nv_bfloat16 g_fp_hi[B_ * PADN * CIN];
__device__ __nv_bfloat16 g_fp_lo[B_ * PADN * CIN];
__device__ __nv_bfloat16 g_w_hi[9 * KQ * CIN], g_w_lo[9 * KQ * CIN];
__device__ __nv_bfloat16 g_kw_hi[KQ * KQ], g_kw_lo[KQ * KQ];
__device__ __nv_bfloat16 g_qw_hi[KQ * KQ], g_qw_lo[KQ * KQ];
__device__ __nv_bfloat16 g_x_hi[B_ * HW * KQ], g_x_lo[B_ * HW * KQ];
__device__ float g_keys[B_ * HW * KQ], g_qrs[B_ * HW * KQ];
__device__ float g_k2[B_ * 4096 * KQ], g_q2[B_ * 4096 * KQ];
__device__ float g_k4[B_ * 1024 * KQ], g_q4[B_ * 1024 * KQ];

// ---------------- helpers ----------------
__device__ __forceinline__ uint32_t smem_u32(const void* p) {
    uint32_t a;
    asm("{ .reg .u64 t; cvta.to.shared.u64 t, %1; cvt.u32.u64 %0, t; }" : "=r"(a) : "l"(p));
    return a;
}
__device__ __forceinline__ void cp16(uint32_t dst, const void* src) {
    asm volatile("cp.async.cg.shared.global [%0], [%1], 16;" :: "r"(dst), "l"(src) : "memory");
}
#define CP_COMMIT() asm volatile("cp.async.commit_group;" ::: "memory")
#define CP_WAIT(n)  asm volatile("cp.async.wait_group %0;" :: "n"(n) : "memory")

__device__ __forceinline__ void ldsm_x4(uint32_t* r, uint32_t addr) {
    asm volatile("ldmatrix.sync.aligned.m8n8.x4.shared.b16 {%0,%1,%2,%3}, [%4];"
                 : "=r"(r[0]), "=r"(r[1]), "=r"(r[2]), "=r"(r[3]) : "r"(addr));
}
__device__ __forceinline__ void ldsm_x2(uint32_t* r, uint32_t addr) {
    asm volatile("ldmatrix.sync.aligned.m8n8.x2.shared.b16 {%0,%1}, [%2];"
                 : "=r"(r[0]), "=r"(r[1]) : "r"(addr));
}
__device__ __forceinline__ void mma16816(float* c, const uint32_t* a, const uint32_t* b) {
    asm volatile("mma.sync.aligned.m16n8k16.row.col.f32.bf16.bf16.f32 "
                 "{%0,%1,%2,%3}, {%4,%5,%6,%7}, {%8,%9}, {%0,%1,%2,%3};"
                 : "+f"(c[0]), "+f"(c[1]), "+f"(c[2]), "+f"(c[3])
                 : "r"(a[0]), "r"(a[1]), "r"(a[2]), "r"(a[3]), "r"(b[0]), "r"(b[1]));
}
__device__ __forceinline__ uint32_t pack2(__nv_bfloat16 a, __nv_bfloat16 b) {
    return (uint32_t)__bfloat16_as_ushort(a) | ((uint32_t)__bfloat16_as_ushort(b) << 16);
}

// Stage 4 tiles (A_hi, A_lo, B_hi, B_lo), each [128 rows x 64 bf16] SW128-swizzled.
__device__ __forceinline__ void stage_tiles(uint32_t sdst,
    const __nv_bfloat16* a_hi, const __nv_bfloat16* a_lo,
    const __nv_bfloat16* b_hi, const __nv_bfloat16* b_lo,
    int a_stride, int b_stride, int tid)
{
    #pragma unroll
    for (int s = 0; s < 16; s++) {
        int i = tid + s * 256;
        int tile = i >> 10, j = i & 1023, r = j >> 3, c16 = j & 7;
        const __nv_bfloat16* src;
        if (tile == 0)      src = a_hi + (size_t)r * a_stride;
        else if (tile == 1) src = a_lo + (size_t)r * a_stride;
        else if (tile == 2) src = b_hi + (size_t)r * b_stride;
        else                src = b_lo + (size_t)r * b_stride;
        cp16(sdst + tile * 16384 + SW(r * 128 + c16 * 16), src + c16 * 8);
    }
}

// One 128x128x64 split-GEMM step on a staged buffer (hi*hi + hi*lo + lo*hi).
__device__ __forceinline__ void compute_tile(float acc[2][8][4], uint32_t tbase,
                                             int m0, int n0, int lane)
{
    #pragma unroll
    for (int ks = 0; ks < 4; ks++) {
        uint32_t bh[8][2], bl[8][2];
        const int bro = (n0 + (lane & 7)) * 128 + ks * 32 + ((lane >> 3) & 1) * 16;
        #pragma unroll
        for (int nt = 0; nt < 8; nt++) {
            ldsm_x2(bh[nt], tbase + 32768 + SW(bro + nt * 1024));
            ldsm_x2(bl[nt], tbase + 49152 + SW(bro + nt * 1024));
        }
        const int aro = (m0 + (lane & 15)) * 128 + ks * 32 + (lane >> 4) * 16;
        #pragma unroll
        for (int mt = 0; mt < 2; mt++) {
            uint32_t ah[4], al[4];
            ldsm_x4(ah, tbase + SW(aro + mt * 2048));
            ldsm_x4(al, tbase + 16384 + SW(aro + mt * 2048));
            #pragma unroll
            for (int nt = 0; nt < 8; nt++) {
                mma16816(acc[mt][nt], ah, bh[nt]);
                mma16816(acc[mt][nt], ah, bl[nt]);
                mma16816(acc[mt][nt], al, bh[nt]);
            }
        }
    }
}

// ---------------- prep kernels ----------------
__global__ __launch_bounds__(256) void zero_pad_kernel() {
    uint32_t idx = blockIdx.x * 256 + threadIdx.x;
    const uint32_t n32 = (B_ * PADN * CIN) / 2;
    if (idx < n32) {
        ((uint32_t*)g_fp_hi)[idx] = 0;
        ((uint32_t*)g_fp_lo)[idx] = 0;
    }
}

__global__ __launch_bounds__(256) void transpose_cv(const float* __restrict__ feats) {
    __shared__ float s[32][33];
    int bid = blockIdx.x;
    int cblk = bid & 7;
    int xblk = (bid >> 3) & 3;
    int y    = (bid >> 5) & 127;
    int b    = bid >> 12;
    int c0 = cblk * 32, x0 = xblk * 32;
    int tid = threadIdx.x;

    #pragma unroll
    for (int r = 0; r < 4; r++) {
        int ci = (tid >> 5) + r * 8;
        int xi = tid & 31;
        s[ci][xi] = feats[(((size_t)b * CIN + c0 + ci) * Hdim + y) * Wdim + x0 + xi];
    }
    __syncthreads();
    #pragma unroll
    for (int r = 0; r < 4; r++) {
        int xj = (tid >> 5) + r * 8;
        int cj = tid & 31;
        float v = s[cj][xj];
        __nv_bfloat16 hi = __float2bfloat16(v);
        float lo = v - __bfloat162float(hi);
        size_t idx = ((size_t)b * PADN + (size_t)(y + 1) * PADW + (x0 + xj + 1)) * CIN + c0 + cj;
        g_fp_hi[idx] = hi;
        g_fp_lo[idx] = __float2bfloat16(lo);
    }
}

__global__ __launch_bounds__(256) void prep_w2(const float* __restrict__ conv_w,
                                               const float* __restrict__ key_w,
                                               const float* __restrict__ query_w) {
    int i = blockIdx.x * 256 + threadIdx.x;
    if (i < 9 * KQ * CIN) {
        int t = i / (KQ * CIN);
        int rem = i % (KQ * CIN);
        int k = rem / CIN, c = rem % CIN;
        float v = conv_w[((size_t)k * CIN + c) * 9 + t];
        __nv_bfloat16 hi = __float2bfloat16(v);
        g_w_hi[i] = hi;
        g_w_lo[i] = __float2bfloat16(v - __bfloat162float(hi));
    }
    if (i < KQ * KQ) {
        float v = key_w[i];
        __nv_bfloat16 hi = __float2bfloat16(v);
        g_kw_hi[i] = hi;
        g_kw_lo[i] = __float2bfloat16(v - __bfloat162float(hi));
        float u = query_w[i];
        __nv_bfloat16 uhi = __float2bfloat16(u);
        g_qw_hi[i] = uhi;
        g_qw_lo[i] = __float2bfloat16(u - __bfloat162float(uhi));
    }
}

// ---------------- conv3x3 as implicit GEMM via mma.sync bf16 ----------------
// CTA = one (b, y): M=128 x-positions, N=128 out channels, K = 9 taps x 256 c.
__global__ __launch_bounds__(256, 1) void conv_mma(const float* __restrict__ conv_b) {
    extern __shared__ char smem[];
    const uint32_t sb0 = smem_u32(smem);
    const int tid = threadIdx.x, warp = tid >> 5, lane = tid & 31;
    const int y = blockIdx.x, bb = blockIdx.y;
    const int m0 = (warp & 3) * 32, n0 = (warp >> 2) * 64;

    float acc[2][8][4];
    #pragma unroll
    for (int mt = 0; mt < 2; mt++)
        #pragma unroll
        for (int nt = 0; nt < 8; nt++)
            #pragma unroll
            for (int e = 0; e < 4; e++) acc[mt][nt][e] = 0.f;

    // chunk idx -> (tap = idx>>2, cc = idx&3)
    {
        const size_t arow0 = ((size_t)bb * PADN + (size_t)y * PADW) * CIN;
        size_t ar = arow0;   // tap 0: dy=0,dx=0, cc=0
        size_t wr = 0;
        stage_tiles(sb0, g_fp_hi + ar, g_fp_lo + ar, g_w_hi + wr, g_w_lo + wr,
                    CIN, CIN, tid);
        CP_COMMIT();
        for (int idx = 0; idx < 36; idx++) {
            if (idx + 1 < 36) {
                int nid = idx + 1;
                int tap = nid >> 2, cc = nid & 3;
                int dy = tap / 3, dx = tap % 3;
                size_t arow = ((size_t)bb * PADN + (size_t)(y + dy) * PADW + dx) * CIN + cc * 64;
                size_t wrow = (size_t)tap * KQ * CIN + cc * 64;
                stage_tiles(sb0 + (uint32_t)(nid & 1) * 65536u,
                            g_fp_hi + arow, g_fp_lo + arow,
                            g_w_hi + wrow, g_w_lo + wrow, CIN, CIN, tid);
                CP_COMMIT();
                CP_WAIT(1);
            } else {
                CP_WAIT(0);
            }
            __syncthreads();
            compute_tile(acc, sb0 + (uint32_t)(idx & 1) * 65536u, m0, n0, lane);
            __syncthreads();
        }
    }

    // epilogue: add bias, split to bf16 hi/lo, store x
    const size_t mg = (size_t)bb * HW + (size_t)y * Wdim;
    #pragma unroll
    for (int mt = 0; mt < 2; mt++) {
        int mrow = m0 + mt * 16 + (lane >> 2);
        #pragma unroll
        for (int nt = 0; nt < 8; nt++) {
            int n = n0 + nt * 8 + (lane & 3) * 2;
            float b0v = conv_b[n], b1v = conv_b[n + 1];
            #pragma unroll
            for (int half = 0; half < 2; half++) {
                float v0 = acc[mt][nt][half * 2 + 0] + b0v;
                float v1 = acc[mt][nt][half * 2 + 1] + b1v;
                __nv_bfloat16 h0 = __float2bfloat16(v0), h1 = __float2bfloat16(v1);
                float l0 = v0 - __bfloat162float(h0);
                float l1 = v1 - __bfloat162float(h1);
                size_t o = (mg + mrow + half * 8) * KQ + n;
                *(uint32_t*)&g_x_hi[o] = pack2(h0, h1);
                *(uint32_t*)&g_x_lo[o] = pack2(__float2bfloat16(l0), __float2bfloat16(l1));
            }
        }
    }
}

// ---------------- keys/queries projection via mma.sync bf16 ----------------
// CTA = 128 m-rows; blockIdx.y selects keys(0)/queries(1). K=128 c.
__global__ __launch_bounds__(256, 1) void proj_mma(const float* __restrict__ key_b,
                                                   const float* __restrict__ query_b) {
    extern __shared__ char smem[];
    const uint32_t sb0 = smem_u32(smem);
    const int tid = threadIdx.x, warp = tid >> 5, lane = tid & 31;
    const int which = blockIdx.y;
    const size_t mbase = (size_t)blockIdx.x * 128;
    const int m0 = (warp & 3) * 32, n0 = (warp >> 2) * 64;

    const __nv_bfloat16* w_hi = which ? g_qw_hi : g_kw_hi;
    const __nv_bfloat16* w_lo = which ? g_qw_lo : g_kw_lo;

    float acc[2][8][4];
    #pragma unroll
    for (int mt = 0; mt < 2; mt++)
        #pragma unroll
        for (int nt = 0; nt < 8; nt++)
            #pragma unroll
            for (int e = 0; e < 4; e++) acc[mt][nt][e] = 0.f;

    stage_tiles(sb0, g_x_hi + mbase * KQ, g_x_lo + mbase * KQ, w_hi, w_lo, KQ, KQ, tid);
    CP_COMMIT();
    for (int cc = 0; cc < 2; cc++) {
        if (cc == 0) {
            stage_tiles(sb0 + 65536u, g_x_hi + mbase * KQ + 64, g_x_lo + mbase * KQ + 64,
                        w_hi + 64, w_lo + 64, KQ, KQ, tid);
            CP_COMMIT();
            CP_WAIT(1);
        } else {
            CP_WAIT(0);
        }
        __syncthreads();
        compute_tile(acc, sb0 + (uint32_t)cc * 65536u, m0, n0, lane);
        __syncthreads();
    }

    const float* bias = which ? query_b : key_b;
    float* out = which ? g_qrs : g_keys;
    #pragma unroll
    for (int mt = 0; mt < 2; mt++) {
        int mrow = m0 + mt * 16 + (lane >> 2);
        #pragma unroll
        for (int nt = 0; nt < 8; nt++) {
            int n = n0 + nt * 8 + (lane & 3) * 2;
            float b0v = bias[n], b1v = bias[n + 1];
            #pragma unroll
            for (int half = 0; half < 2; half++) {
                float2 v = make_float2(acc[mt][nt][half * 2 + 0] + b0v,
                                       acc[mt][nt][half * 2 + 1] + b1v);
                *(float2*)&out[(mbase + mrow + half * 8) * KQ + n] = v;
            }
        }
    }
}

// ---------------- avg pool s x s, [b][m][c] -> [b][n][c] ----------------
__global__ __launch_bounds__(256) void pool_kernel(int s) {
    const float* in = blockIdx.z ? g_qrs : g_keys;
    float* out;
    const int hp = Hdim / s;
    const int n  = hp * hp;
    if (s == 2) out = blockIdx.z ? g_q2 : g_k2;
    else        out = blockIdx.z ? g_q4 : g_k4;

    int idx = blockIdx.x * 256 + threadIdx.x;
    if (idx >= B_ * n * 32) return;
    int c4 = idx & 31;
    int nn = (idx >> 5) % n;
    int b  = idx / (n * 32);
    int yy = nn / hp, xx = nn % hp;

    float4 acc = make_float4(0.f, 0.f, 0.f, 0.f);
    for (int ry = 0; ry < s; ry++)
        for (int rx = 0; rx < s; rx++) {
            int m = (yy * s + ry) * Wdim + xx * s + rx;
            float4 v = *(const float4*)&in[((size_t)b * HW + m) * KQ + c4 * 4];
            acc.x += v.x; acc.y += v.y; acc.z += v.z; acc.w += v.w;
        }
    float inv = 1.f / (float)(s * s);
    acc.x *= inv; acc.y *= inv; acc.z *= inv; acc.w *= inv;
    *(float4*)&out[((size_t)b * n + nn) * KQ + c4 * 4] = acc;
}

// ---------------- logits ----------------
__global__ __launch_bounds__(256) void logits_kernel(const int* __restrict__ inds,
                                                     float* __restrict__ out,
                                                     int n, int n_off, int lvl) {
    const float* q;
    const float* k;
    if (lvl == 0)      { q = g_qrs; k = g_keys; }
    else if (lvl == 1) { q = g_q2;  k = g_k2;  }
    else               { q = g_q4;  k = g_k4;  }

    const int warp = threadIdx.x >> 5;
    const int lane = threadIdx.x & 31;
    const int nn = blockIdx.x * 8 + warp;
    const int b  = blockIdx.z;
    if (nn >= n) return;

    float4 qv = *(const float4*)&q[((size_t)b * n + nn) * KQ + lane * 4];
    const int* ip = inds + ((size_t)b * n + nn) * 32;

    float myval = 0.f;
    #pragma unroll 4
    for (int s = 0; s < 32; s++) {
        int ind = ip[s];
        float4 kv = *(const float4*)&k[((size_t)b * n + ind) * KQ + lane * 4];
        float p = qv.x * kv.x + qv.y * kv.y + qv.z * kv.z + qv.w * kv.w;
        p += __shfl_xor_sync(0xffffffffu, p, 1);
        p += __shfl_xor_sync(0xffffffffu, p, 2);
        p += __shfl_xor_sync(0xffffffffu, p, 4);
        p += __shfl_xor_sync(0xffffffffu, p, 8);
        p += __shfl_xor_sync(0xffffffffu, p, 16);
        if (lane == s) myval = p * SCALE;
    }
    out[((size_t)b * NTOT + n_off + nn) * 32 + lane] = myval;
}

// ---------------- launch ----------------
extern "C" void kernel_launch(void* const* d_in, const int* in_sizes, int n_in,
                              void* d_out, int out_size) {
    const float* feats   = (const float*)d_in[0];
    const float* conv_w  = (const float*)d_in[1];
    const float* conv_b  = (const float*)d_in[2];
    const float* key_w   = (const float*)d_in[3];
    const float* key_b   = (const float*)d_in[4];
    const float* query_w = (const float*)d_in[5];
    const float* query_b = (const float*)d_in[6];
    const int* si2 = (const int*)d_in[7];
    const int* si3 = (const int*)d_in[8];
    const int* si4 = (const int*)d_in[9];
    float* out = (float*)d_out;

    static bool attr_set = false;
    if (!attr_set) {
        cudaFuncSetAttribute(conv_mma, cudaFuncAttributeMaxDynamicSharedMemorySize, SMEM_BYTES);
        cudaFuncSetAttribute(proj_mma, cudaFuncAttributeMaxDynamicSharedMemorySize, SMEM_BYTES);
        attr_set = true;
    }

    zero_pad_kernel<<<(B_ * PADN * CIN / 2 + 255) / 256, 256>>>();
    transpose_cv<<<8192, 256>>>(feats);
    prep_w2<<<(9 * KQ * CIN + 255) / 256, 256>>>(conv_w, key_w, query_w);
    conv_mma<<<dim3(Hdim, B_), 256, SMEM_BYTES>>>(conv_b);
    proj_mma<<<dim3((B_ * HW) / 128, 2), 256, SMEM_BYTES>>>(key_b, query_b);
    pool_kernel<<<dim3((B_ * 4096 * 32 + 255) / 256, 1, 2), 256>>>(2);
    pool_kernel<<<dim3((B_ * 1024 * 32 + 255) / 256, 1, 2), 256>>>(4);
    logits_kernel<<<dim3(16384 / 8, 1, B_), 256>>>(si2, out, 16384, 0, 0);
    logits_kernel<<<dim3(4096 / 8, 1, B_), 256>>>(si3, out, 4096, 16384, 1);
    logits_kernel<<<dim3(1024 / 8, 1, B_), 256>>>(si4, out, 1024, 20480, 2);
}

// round 6
// speedup vs baseline: 2.3867x; 1.0733x over previous
#include <cuda_runtime.h>
#include <cuda_bf16.h>
#include <cstdint>

#define B_      2
#define CIN     256
#define Hdim    128
#define Wdim    128
#define KQ      128
#define HW      16384
#define NTOT    21504   // 16384 + 4096 + 1024
#define SCALE   0.08838834764831845f
#define PADW    130
#define PADN    16900   // 130*130

#define SMEM_BYTES 196608   // 3 stages x 64KB
#define SW(o) ((uint32_t)(o) ^ ((((uint32_t)(o)) >> 3) & 0x70u))

// ---------------- device scratch ----------------
__device__ __nv_bfloat16 g_fp_hi[B_ * PADN * CIN];
__device__ __nv_bfloat16 g_fp_lo[B_ * PADN * CIN];
__device__ __nv_bfloat16 g_w_hi[9 * KQ * CIN], g_w_lo[9 * KQ * CIN];
__device__ __nv_bfloat16 g_kw_hi[KQ * KQ], g_kw_lo[KQ * KQ];
__device__ __nv_bfloat16 g_qw_hi[KQ * KQ], g_qw_lo[KQ * KQ];
__device__ float g_keys[B_ * HW * KQ], g_qrs[B_ * HW * KQ];
__device__ float g_k2[B_ * 4096 * KQ], g_q2[B_ * 4096 * KQ];
__device__ float g_k4[B_ * 1024 * KQ], g_q4[B_ * 1024 * KQ];

// ---------------- helpers ----------------
__device__ __forceinline__ uint32_t smem_u32(const void* p) {
    uint32_t a;
    asm("{ .reg .u64 t; cvta.to.shared.u64 t, %1; cvt.u32.u64 %0, t; }" : "=r"(a) : "l"(p));
    return a;
}
__device__ __forceinline__ void cp16(uint32_t dst, const void* src) {
    asm volatile("cp.async.cg.shared.global [%0], [%1], 16;" :: "r"(dst), "l"(src) : "memory");
}
#define CP_COMMIT() asm volatile("cp.async.commit_group;" ::: "memory")
#define CP_WAIT(n)  asm volatile("cp.async.wait_group %0;" :: "n"(n) : "memory")

__device__ __forceinline__ void ldsm_x4(uint32_t* r, uint32_t addr) {
    asm volatile("ldmatrix.sync.aligned.m8n8.x4.shared.b16 {%0,%1,%2,%3}, [%4];"
                 : "=r"(r[0]), "=r"(r[1]), "=r"(r[2]), "=r"(r[3]) : "r"(addr));
}
__device__ __forceinline__ void ldsm_x2(uint32_t* r, uint32_t addr) {
    asm volatile("ldmatrix.sync.aligned.m8n8.x2.shared.b16 {%0,%1}, [%2];"
                 : "=r"(r[0]), "=r"(r[1]) : "r"(addr));
}
__device__ __forceinline__ void mma16816(float* c, const uint32_t* a, const uint32_t* b) {
    asm volatile("mma.sync.aligned.m16n8k16.row.col.f32.bf16.bf16.f32 "
                 "{%0,%1,%2,%3}, {%4,%5,%6,%7}, {%8,%9}, {%0,%1,%2,%3};"
                 : "+f"(c[0]), "+f"(c[1]), "+f"(c[2]), "+f"(c[3])
                 : "r"(a[0]), "r"(a[1]), "r"(a[2]), "r"(a[3]), "r"(b[0]), "r"(b[1]));
}
__device__ __forceinline__ uint32_t pack2(__nv_bfloat16 a, __nv_bfloat16 b) {
    return (uint32_t)__bfloat16_as_ushort(a) | ((uint32_t)__bfloat16_as_ushort(b) << 16);
}

// Stage 4 tiles (A_hi, A_lo, B_hi, B_lo), each [128 rows x 64 bf16] SW128-swizzled.
__device__ __forceinline__ void stage_tiles(uint32_t sdst,
    const __nv_bfloat16* a_hi, const __nv_bfloat16* a_lo,
    const __nv_bfloat16* b_hi, const __nv_bfloat16* b_lo,
    int a_stride, int b_stride, int tid)
{
    #pragma unroll
    for (int s = 0; s < 16; s++) {
        int i = tid + s * 256;
        int tile = i >> 10, j = i & 1023, r = j >> 3, c16 = j & 7;
        const __nv_bfloat16* src;
        if (tile == 0)      src = a_hi + (size_t)r * a_stride;
        else if (tile == 1) src = a_lo + (size_t)r * a_stride;
        else if (tile == 2) src = b_hi + (size_t)r * b_stride;
        else                src = b_lo + (size_t)r * b_stride;
        cp16(sdst + tile * 16384 + SW(r * 128 + c16 * 16), src + c16 * 8);
    }
}

// One 128x128x64 split-GEMM step (hi*hi + hi*lo + lo*hi), generalized tile bases.
__device__ __forceinline__ void compute_tile2(float acc[2][8][4],
    uint32_t a_hi, uint32_t a_lo, uint32_t b_hi, uint32_t b_lo,
    int m0, int n0, int lane)
{
    #pragma unroll
    for (int ks = 0; ks < 4; ks++) {
        uint32_t bhf[8][2], blf[8][2];
        const int bro = (n0 + (lane & 7)) * 128 + ks * 32 + ((lane >> 3) & 1) * 16;
        #pragma unroll
        for (int nt = 0; nt < 8; nt++) {
            ldsm_x2(bhf[nt], b_hi + SW(bro + nt * 1024));
            ldsm_x2(blf[nt], b_lo + SW(bro + nt * 1024));
        }
        const int aro = (m0 + (lane & 15)) * 128 + ks * 32 + (lane >> 4) * 16;
        #pragma unroll
        for (int mt = 0; mt < 2; mt++) {
            uint32_t ah[4], al[4];
            ldsm_x4(ah, a_hi + SW(aro + mt * 2048));
            ldsm_x4(al, a_lo + SW(aro + mt * 2048));
            #pragma unroll
            for (int nt = 0; nt < 8; nt++) {
                mma16816(acc[mt][nt], ah, bhf[nt]);
                mma16816(acc[mt][nt], ah, blf[nt]);
                mma16816(acc[mt][nt], al, bhf[nt]);
            }
        }
    }
}

// ---------------- prep kernels ----------------
// Zero only the padding border of g_fp_hi/lo (interior fully overwritten by transpose_cv).
__global__ __launch_bounds__(256) void zero_border_kernel() {
    // 516 border cells per batch; each thread zeroes 16B (8 ch) in both arrays.
    int idx = blockIdx.x * 256 + threadIdx.x;
    const int per_b = 516 * 32;             // cells * (256ch/8)
    if (idx >= B_ * per_b) return;
    int b = idx / per_b;
    int r = idx % per_b;
    int cell = r >> 5;          // 0..515
    int cgrp = r & 31;          // 8-channel group
    int y, x;
    if (cell < 130)      { y = 0;   x = cell; }
    else if (cell < 260) { y = 129; x = cell - 130; }
    else if (cell < 388) { y = 1 + (cell - 260); x = 0; }
    else                 { y = 1 + (cell - 388); x = 129; }
    size_t o = ((size_t)b * PADN + (size_t)y * PADW + x) * CIN + cgrp * 8;
    *(float4*)&g_fp_hi[o] = make_float4(0.f, 0.f, 0.f, 0.f);
    *(float4*)&g_fp_lo[o] = make_float4(0.f, 0.f, 0.f, 0.f);
}

__global__ __launch_bounds__(256) void transpose_cv(const float* __restrict__ feats) {
    __shared__ float s[32][33];
    int bid = blockIdx.x;
    int cblk = bid & 7;
    int xblk = (bid >> 3) & 3;
    int y    = (bid >> 5) & 127;
    int b    = bid >> 12;
    int c0 = cblk * 32, x0 = xblk * 32;
    int tid = threadIdx.x;

    #pragma unroll
    for (int r = 0; r < 4; r++) {
        int ci = (tid >> 5) + r * 8;
        int xi = tid & 31;
        s[ci][xi] = feats[(((size_t)b * CIN + c0 + ci) * Hdim + y) * Wdim + x0 + xi];
    }
    __syncthreads();
    #pragma unroll
    for (int r = 0; r < 4; r++) {
        int xj = (tid >> 5) + r * 8;
        int cj = tid & 31;
        float v = s[cj][xj];
        __nv_bfloat16 hi = __float2bfloat16(v);
        float lo = v - __bfloat162float(hi);
        size_t idx = ((size_t)b * PADN + (size_t)(y + 1) * PADW + (x0 + xj + 1)) * CIN + c0 + cj;
        g_fp_hi[idx] = hi;
        g_fp_lo[idx] = __float2bfloat16(lo);
    }
}

__global__ __launch_bounds__(256) void prep_w2(const float* __restrict__ conv_w,
                                               const float* __restrict__ key_w,
                                               const float* __restrict__ query_w) {
    int i = blockIdx.x * 256 + threadIdx.x;
    if (i < 9 * KQ * CIN) {
        int t = i / (KQ * CIN);
        int rem = i % (KQ * CIN);
        int k = rem / CIN, c = rem % CIN;
        float v = conv_w[((size_t)k * CIN + c) * 9 + t];
        __nv_bfloat16 hi = __float2bfloat16(v);
        g_w_hi[i] = hi;
        g_w_lo[i] = __float2bfloat16(v - __bfloat162float(hi));
    }
    if (i < KQ * KQ) {
        float v = key_w[i];
        __nv_bfloat16 hi = __float2bfloat16(v);
        g_kw_hi[i] = hi;
        g_kw_lo[i] = __float2bfloat16(v - __bfloat162float(hi));
        float u = query_w[i];
        __nv_bfloat16 uhi = __float2bfloat16(u);
        g_qw_hi[i] = uhi;
        g_qw_lo[i] = __float2bfloat16(u - __bfloat162float(uhi));
    }
}

// ---------------- fused conv3x3 + projections via mma.sync bf16 ----------------
// CTA = one (b, y): M=128 x-positions. Conv: N=128 ch, K=9x256 (36 chunks of 64).
// 3-stage cp.async pipeline, one barrier per chunk. Then x stays in SMEM (bf16
// hi/lo) and keys/queries are computed in-kernel.
__global__ __launch_bounds__(256, 1) void conv_fused(const float* __restrict__ conv_b,
                                                     const float* __restrict__ key_b,
                                                     const float* __restrict__ query_b) {
    extern __shared__ char smem[];
    const uint32_t sb0 = smem_u32(smem);
    const int tid = threadIdx.x, warp = tid >> 5, lane = tid & 31;
    const int y = blockIdx.x, bb = blockIdx.y;
    const int m0 = (warp & 3) * 32, n0 = (warp >> 2) * 64;

    float acc[2][8][4];
    #pragma unroll
    for (int mt = 0; mt < 2; mt++)
        #pragma unroll
        for (int nt = 0; nt < 8; nt++)
            #pragma unroll
            for (int e = 0; e < 4; e++) acc[mt][nt][e] = 0.f;

    const size_t apb = (size_t)bb * PADN;   // padded-batch base

    // chunk nid -> (tap = nid>>2, cc = nid&3); stage into buffer nid%3
    #pragma unroll 1
    for (int nid = 0; nid < 2; nid++) {
        int tap = nid >> 2, cc = nid & 3;
        int dy = tap / 3, dx = tap % 3;
        size_t arow = (apb + (size_t)(y + dy) * PADW + dx) * CIN + cc * 64;
        size_t wrow = (size_t)tap * KQ * CIN + cc * 64;
        stage_tiles(sb0 + (uint32_t)(nid % 3) * 65536u,
                    g_fp_hi + arow, g_fp_lo + arow,
                    g_w_hi + wrow, g_w_lo + wrow, CIN, CIN, tid);
        CP_COMMIT();
    }

    #pragma unroll 1
    for (int idx = 0; idx < 36; idx++) {
        CP_WAIT(1);
        __syncthreads();
        int nid = idx + 2;
        if (nid < 36) {
            int tap = nid >> 2, cc = nid & 3;
            int dy = tap / 3, dx = tap % 3;
            size_t arow = (apb + (size_t)(y + dy) * PADW + dx) * CIN + cc * 64;
            size_t wrow = (size_t)tap * KQ * CIN + cc * 64;
            stage_tiles(sb0 + (uint32_t)(nid % 3) * 65536u,
                        g_fp_hi + arow, g_fp_lo + arow,
                        g_w_hi + wrow, g_w_lo + wrow, CIN, CIN, tid);
        }
        CP_COMMIT();
        uint32_t tb = sb0 + (uint32_t)(idx % 3) * 65536u;
        compute_tile2(acc, tb, tb + 16384, tb + 32768, tb + 49152, m0, n0, lane);
    }
    __syncthreads();   // all compute done; stage buffers are now free

    // ---- issue proj-weight loads (128KB into region +65536..+196608) ----
    #pragma unroll
    for (int s = 0; s < 32; s++) {
        int i = tid + s * 256;
        int tile = i >> 10, j = i & 1023, r = j >> 3, c16 = j & 7;
        int tg = tile >> 2, lo = (tile >> 1) & 1, cc = tile & 1;
        const __nv_bfloat16* src =
            (tg ? (lo ? g_qw_lo : g_qw_hi) : (lo ? g_kw_lo : g_kw_hi))
            + (size_t)r * KQ + cc * 64 + c16 * 8;
        cp16(sb0 + 65536u + tile * 16384 + SW(r * 128 + c16 * 16), src);
    }
    CP_COMMIT();

    // ---- conv epilogue: bias add, bf16 hi/lo split, x tiles into stage-0 area ----
    // layout: x_hi cc0 @0, x_hi cc1 @16384, x_lo cc0 @32768, x_lo cc1 @49152
    #pragma unroll
    for (int mt = 0; mt < 2; mt++) {
        #pragma unroll
        for (int nt = 0; nt < 8; nt++) {
            int n = n0 + nt * 8 + (lane & 3) * 2;
            float b0v = conv_b[n], b1v = conv_b[n + 1];
            uint32_t tbase = (uint32_t)((n >> 6) * 16384) + (uint32_t)((n & 63) * 2);
            #pragma unroll
            for (int half = 0; half < 2; half++) {
                int mrow = m0 + mt * 16 + (lane >> 2) + half * 8;
                float v0 = acc[mt][nt][half * 2 + 0] + b0v;
                float v1 = acc[mt][nt][half * 2 + 1] + b1v;
                __nv_bfloat16 h0 = __float2bfloat16(v0), h1 = __float2bfloat16(v1);
                float l0 = v0 - __bfloat162float(h0);
                float l1 = v1 - __bfloat162float(h1);
                uint32_t off = SW(mrow * 128 + (n & 63) * 2);
                *(uint32_t*)(smem + (tbase & ~127u) + off)          = pack2(h0, h1);
                *(uint32_t*)(smem + 32768 + (tbase & ~127u) + off)  =
                    pack2(__float2bfloat16(l0), __float2bfloat16(l1));
            }
        }
    }
    CP_WAIT(0);
    __syncthreads();

    // ---- projections: out[m][k] = sum_c x[m][c] * w[k][c] + bias ----
    const size_t mg = (size_t)bb * HW + (size_t)y * Wdim;
    #pragma unroll 1
    for (int tg = 0; tg < 2; tg++) {
        #pragma unroll
        for (int mt = 0; mt < 2; mt++)
            #pragma unroll
            for (int nt = 0; nt < 8; nt++)
                #pragma unroll
                for (int e = 0; e < 4; e++) acc[mt][nt][e] = 0.f;

        uint32_t wbase = sb0 + 65536u + (uint32_t)tg * 65536u;
        #pragma unroll
        for (int cc = 0; cc < 2; cc++) {
            compute_tile2(acc,
                          sb0 + cc * 16384u, sb0 + 32768u + cc * 16384u,
                          wbase + cc * 16384u, wbase + 32768u + cc * 16384u,
                          m0, n0, lane);
        }

        const float* bias = tg ? query_b : key_b;
        float* out = tg ? g_qrs : g_keys;
        #pragma unroll
        for (int mt = 0; mt < 2; mt++) {
            #pragma unroll
            for (int nt = 0; nt < 8; nt++) {
                int n = n0 + nt * 8 + (lane & 3) * 2;
                float b0v = bias[n], b1v = bias[n + 1];
                #pragma unroll
                for (int half = 0; half < 2; half++) {
                    int mrow = m0 + mt * 16 + (lane >> 2) + half * 8;
                    float2 v = make_float2(acc[mt][nt][half * 2 + 0] + b0v,
                                           acc[mt][nt][half * 2 + 1] + b1v);
                    *(float2*)&out[(mg + mrow) * KQ + n] = v;
                }
            }
        }
    }
}

// ---------------- avg pool s x s, [b][m][c] -> [b][n][c] ----------------
__global__ __launch_bounds__(256) void pool_kernel(int s) {
    const float* in = blockIdx.z ? g_qrs : g_keys;
    float* out;
    const int hp = Hdim / s;
    const int n  = hp * hp;
    if (s == 2) out = blockIdx.z ? g_q2 : g_k2;
    else        out = blockIdx.z ? g_q4 : g_k4;

    int idx = blockIdx.x * 256 + threadIdx.x;
    if (idx >= B_ * n * 32) return;
    int c4 = idx & 31;
    int nn = (idx >> 5) % n;
    int b  = idx / (n * 32);
    int yy = nn / hp, xx = nn % hp;

    float4 acc = make_float4(0.f, 0.f, 0.f, 0.f);
    for (int ry = 0; ry < s; ry++)
        for (int rx = 0; rx < s; rx++) {
            int m = (yy * s + ry) * Wdim + xx * s + rx;
            float4 v = *(const float4*)&in[((size_t)b * HW + m) * KQ + c4 * 4];
            acc.x += v.x; acc.y += v.y; acc.z += v.z; acc.w += v.w;
        }
    float inv = 1.f / (float)(s * s);
    acc.x *= inv; acc.y *= inv; acc.z *= inv; acc.w *= inv;
    *(float4*)&out[((size_t)b * n + nn) * KQ + c4 * 4] = acc;
}

// ---------------- logits ----------------
__global__ __launch_bounds__(256) void logits_kernel(const int* __restrict__ inds,
                                                     float* __restrict__ out,
                                                     int n, int n_off, int lvl) {
    const float* q;
    const float* k;
    if (lvl == 0)      { q = g_qrs; k = g_keys; }
    else if (lvl == 1) { q = g_q2;  k = g_k2;  }
    else               { q = g_q4;  k = g_k4;  }

    const int warp = threadIdx.x >> 5;
    const int lane = threadIdx.x & 31;
    const int nn = blockIdx.x * 8 + warp;
    const int b  = blockIdx.z;
    if (nn >= n) return;

    float4 qv = *(const float4*)&q[((size_t)b * n + nn) * KQ + lane * 4];
    const int* ip = inds + ((size_t)b * n + nn) * 32;

    float myval = 0.f;
    #pragma unroll 4
    for (int s = 0; s < 32; s++) {
        int ind = ip[s];
        float4 kv = *(const float4*)&k[((size_t)b * n + ind) * KQ + lane * 4];
        float p = qv.x * kv.x + qv.y * kv.y + qv.z * kv.z + qv.w * kv.w;
        p += __shfl_xor_sync(0xffffffffu, p, 1);
        p += __shfl_xor_sync(0xffffffffu, p, 2);
        p += __shfl_xor_sync(0xffffffffu, p, 4);
        p += __shfl_xor_sync(0xffffffffu, p, 8);
        p += __shfl_xor_sync(0xffffffffu, p, 16);
        if (lane == s) myval = p * SCALE;
    }
    out[((size_t)b * NTOT + n_off + nn) * 32 + lane] = myval;
}

// ---------------- launch ----------------
extern "C" void kernel_launch(void* const* d_in, const int* in_sizes, int n_in,
                              void* d_out, int out_size) {
    const float* feats   = (const float*)d_in[0];
    const float* conv_w  = (const float*)d_in[1];
    const float* conv_b  = (const float*)d_in[2];
    const float* key_w   = (const float*)d_in[3];
    const float* key_b   = (const float*)d_in[4];
    const float* query_w = (const float*)d_in[5];
    const float* query_b = (const float*)d_in[6];
    const int* si2 = (const int*)d_in[7];
    const int* si3 = (const int*)d_in[8];
    const int* si4 = (const int*)d_in[9];
    float* out = (float*)d_out;

    static bool attr_set = false;
    if (!attr_set) {
        cudaFuncSetAttribute(conv_fused, cudaFuncAttributeMaxDynamicSharedMemorySize, SMEM_BYTES);
        attr_set = true;
    }

    zero_border_kernel<<<(B_ * 516 * 32 + 255) / 256, 256>>>();
    transpose_cv<<<8192, 256>>>(feats);
    prep_w2<<<(9 * KQ * CIN + 255) / 256, 256>>>(conv_w, key_w, query_w);
    conv_fused<<<dim3(Hdim, B_), 256, SMEM_BYTES>>>(conv_b, key_b, query_b);
    pool_kernel<<<dim3((B_ * 4096 * 32 + 255) / 256, 1, 2), 256>>>(2);
    pool_kernel<<<dim3((B_ * 1024 * 32 + 255) / 256, 1, 2), 256>>>(4);
    logits_kernel<<<dim3(16384 / 8, 1, B_), 256>>>(si2, out, 16384, 0, 0);
    logits_kernel<<<dim3(4096 / 8, 1, B_), 256>>>(si3, out, 4096, 16384, 1);
    logits_kernel<<<dim3(1024 / 8, 1, B_), 256>>>(si4, out, 1024, 20480, 2);
}